// round 17
// baseline (speedup 1.0000x reference)
#include <cuda_runtime.h>
#include <cuda.h>
#include <stdint.h>

#define SEQ   4096
#define NPOS  32768
#define SLOT  80
#define ROW_BYTES (SLOT * 4)                 // 320
#define NTAB  16
#define POS_BYTES (NTAB * ROW_BYTES)         // 5120
#define P8    8                              // positions per block (primary kernel)
#define TAB8_STRIDE (P8 * ROW_BYTES)         // 2560 per table (8 rows)
#define WARP8_BYTES (4 * TAB8_STRIDE)        // 10240 per warp (4 tables)
#define STAGE8_BYTES (NTAB * TAB8_STRIDE)    // 40960
#define G8_BLOCKS (NPOS / P8)                // 4096
#define G8_THREADS 128

// R14-fallback constants
#define P4    4
#define TAB_STRIDE (P4 * ROW_BYTES)          // 1280
#define STAGE_BYTES (NTAB * TAB_STRIDE)      // 20480
#define G4_BLOCKS (NPOS / P4)                // 8192
#define WARP_BYTES (4 * TAB_STRIDE)          // 5120

__constant__ unsigned int c_sizes[16] = {
    6619u, 6637u, 6653u, 6659u, 6661u, 6673u, 6679u, 6689u,
    65521u, 65537u, 65539u, 65543u, 65551u, 65557u, 65563u, 65579u
};

static const unsigned int h_sizes[16] = {
    6619u, 6637u, 6653u, 6659u, 6661u, 6673u, 6679u, 6689u,
    65521u, 65537u, 65539u, 65543u, 65551u, 65557u, 65563u, 65579u
};

struct Tables { const float* t[16]; };
struct TMaps  { CUtensorMap m[17]; };        // 16 tables + 1 output (3D)

__device__ __forceinline__ uint32_t smem_u32(const void* p) {
    uint32_t a;
    asm("{ .reg .u64 tmp; cvta.to.shared.u64 tmp, %1; cvt.u32.u64 %0, tmp; }"
        : "=r"(a) : "l"(p));
    return a;
}

__device__ __forceinline__ unsigned long long hash_idx(
    const int* __restrict__ ids, const int* __restrict__ seeds,
    int tab, int pos, unsigned long long ts)
{
    const int head = tab & 7;
    const int s    = pos & (SEQ - 1);
    const unsigned long long id0 = (unsigned int)__ldg(ids + pos);
    const unsigned long long id1 =
        (s >= 1) ? (unsigned long long)(unsigned int)__ldg(ids + pos - 1) : 0ull;
    unsigned long long h;
    if (tab < 8) {
        h = (id1 * (unsigned long long)(unsigned int)__ldg(seeds + head))
          ^ (id0 * (unsigned long long)(unsigned int)__ldg(seeds + 8 + head));
    } else {
        const unsigned long long id2 =
            (s >= 2) ? (unsigned long long)(unsigned int)__ldg(ids + pos - 2) : 0ull;
        h = (id2 * (unsigned long long)(unsigned int)__ldg(seeds + head))
          ^ (id1 * (unsigned long long)(unsigned int)__ldg(seeds + 8 + head))
          ^ (id0 * (unsigned long long)(unsigned int)__ldg(seeds + 16 + head));
    }
    return h % ts;
}

// ====== PRIMARY: 8 positions/warp — 2x gather4 per table, box-z=8 tensor store ======
__global__ __launch_bounds__(G8_THREADS) void engram_g8_kernel(
    const int* __restrict__ ids,
    const int* __restrict__ seeds,
    const __grid_constant__ TMaps maps)
{
    __shared__ __align__(128) unsigned char stage[STAGE8_BYTES]; // [tab][p0..p7][320B]
    __shared__ __align__(8)  unsigned long long mbar[4];

    const int tid  = threadIdx.x;
    const int w    = tid >> 5;
    const int lane = tid & 31;
    const uint32_t stage_a = smem_u32(stage);
    const uint32_t my_mbar = smem_u32(&mbar[w]);

    if (lane == 0) {
        asm volatile("mbarrier.init.shared.b64 [%0], 1;" :: "r"(my_mbar) : "memory");
        asm volatile("mbarrier.arrive.expect_tx.shared.b64 _, [%0], %1;"
                     :: "r"(my_mbar), "r"((int)WARP8_BYTES) : "memory");
    }
    __syncwarp();

    const int base = blockIdx.x * P8;
    const int t0   = w * 4;

    uint64_t pol_ef, pol_el;
    asm("createpolicy.fractional.L2::evict_first.b64 %0, 1.0;" : "=l"(pol_ef));
    asm("createpolicy.fractional.L2::evict_last.b64 %0, 1.0;"  : "=l"(pol_el));

    // all 32 lanes hash: chunk = lane>>4, tabLocal = (lane>>2)&3, p = (lane&3)+4*chunk
    const int tabL  = (lane >> 2) & 3;
    const int tab   = t0 + tabL;
    const int chunk = lane >> 4;
    const int pos   = base + (lane & 3) + (chunk << 2);
    const unsigned int idx =
        (unsigned int)hash_idx(ids, seeds, tab, pos, (unsigned long long)c_sizes[tab]);

    // leaders: lanes with (lane&3)==0 (8 per warp) gather their (table, chunk)
    const unsigned y0 = __shfl_sync(0xFFFFFFFFu, idx, (lane & 0x1C) | 0);
    const unsigned y1 = __shfl_sync(0xFFFFFFFFu, idx, (lane & 0x1C) | 1);
    const unsigned y2 = __shfl_sync(0xFFFFFFFFu, idx, (lane & 0x1C) | 2);
    const unsigned y3 = __shfl_sync(0xFFFFFFFFu, idx, (lane & 0x1C) | 3);

    const uint32_t tab_base = stage_a + (uint32_t)(w * WARP8_BYTES + tabL * TAB8_STRIDE);

    if ((lane & 3) == 0) {
        const uint32_t dst = tab_base + (uint32_t)chunk * (P4 * ROW_BYTES);
        asm volatile(
            "cp.async.bulk.tensor.2d.shared::cta.global.tile::gather4"
            ".mbarrier::complete_tx::bytes.L2::cache_hint "
            "[%0], [%1, {%2, %3, %4, %5, %6}], [%7], %8;"
            :: "r"(dst), "l"(&maps.m[tab]),
               "r"(0), "r"((int)y0), "r"((int)y1), "r"((int)y2), "r"((int)y3),
               "r"(my_mbar), "l"(pol_el)
            : "memory");
    }

    // warp-local wait for its 10240B
    asm volatile(
        "{\n\t"
        ".reg .pred P1;\n\t"
        "W_%=:\n\t"
        "mbarrier.try_wait.parity.acquire.cta.shared::cta.b64 P1, [%0], 0, 0x989680;\n\t"
        "@P1 bra.uni D_%=;\n\t"
        "bra.uni W_%=;\n\t"
        "D_%=:\n\t"
        "}"
        :: "r"(my_mbar) : "memory");

    // one 3D tensor store per table: box (80,1,8) = 2560B contiguous smem
    if ((lane & 3) == 0 && chunk == 0) {
        asm volatile(
            "cp.async.bulk.tensor.3d.global.shared::cta.tile.bulk_group"
            ".L2::cache_hint "
            "[%0, {%1, %2, %3}], [%4], %5;"
            :: "l"(&maps.m[16]), "r"(0), "r"(tab), "r"(base),
               "r"(tab_base), "l"(pol_ef)
            : "memory");
        asm volatile("cp.async.bulk.commit_group;" ::: "memory");
        asm volatile("cp.async.bulk.wait_group.read 0;" ::: "memory");
    }
}

// ==================== fallback: R14 (47.9us known-good, STG drain) ====================
__global__ __launch_bounds__(G8_THREADS) void engram_g4stg_kernel(
    const int* __restrict__ ids,
    const int* __restrict__ seeds,
    const __grid_constant__ TMaps maps,
    float* __restrict__ out)
{
    __shared__ __align__(128) unsigned char stage[STAGE_BYTES];
    __shared__ __align__(8)  unsigned long long mbar[4];

    const int tid  = threadIdx.x;
    const int w    = tid >> 5;
    const int lane = tid & 31;
    const uint32_t stage_a = smem_u32(stage);
    const uint32_t my_mbar = smem_u32(&mbar[w]);

    if (lane == 0) {
        asm volatile("mbarrier.init.shared.b64 [%0], 1;" :: "r"(my_mbar) : "memory");
        asm volatile("mbarrier.arrive.expect_tx.shared.b64 _, [%0], %1;"
                     :: "r"(my_mbar), "r"((int)WARP_BYTES) : "memory");
    }
    __syncwarp();

    const int base = blockIdx.x * P4;
    const int t0   = w * 4;

    uint64_t pol_el;
    asm("createpolicy.fractional.L2::evict_last.b64 %0, 1.0;" : "=l"(pol_el));

    unsigned int idx = 0;
    if (lane < 16) {
        const int tab = t0 + (lane >> 2);
        const int pos = base + (lane & 3);
        idx = (unsigned int)hash_idx(ids, seeds, tab, pos,
                                     (unsigned long long)c_sizes[tab]);
    }

    const unsigned y0 = __shfl_sync(0xFFFFFFFFu, idx, (lane & 12) | 0);
    const unsigned y1 = __shfl_sync(0xFFFFFFFFu, idx, (lane & 12) | 1);
    const unsigned y2 = __shfl_sync(0xFFFFFFFFu, idx, (lane & 12) | 2);
    const unsigned y3 = __shfl_sync(0xFFFFFFFFu, idx, (lane & 12) | 3);

    if (lane < 16 && (lane & 3) == 0) {
        const int tab = t0 + (lane >> 2);
        const uint32_t dst = stage_a + (uint32_t)tab * TAB_STRIDE;
        asm volatile(
            "cp.async.bulk.tensor.2d.shared::cta.global.tile::gather4"
            ".mbarrier::complete_tx::bytes.L2::cache_hint "
            "[%0], [%1, {%2, %3, %4, %5, %6}], [%7], %8;"
            :: "r"(dst), "l"(&maps.m[tab]),
               "r"(0), "r"((int)y0), "r"((int)y1), "r"((int)y2), "r"((int)y3),
               "r"(my_mbar), "l"(pol_el)
            : "memory");
    }

    asm volatile(
        "{\n\t"
        ".reg .pred P1;\n\t"
        "W_%=:\n\t"
        "mbarrier.try_wait.parity.acquire.cta.shared::cta.b64 P1, [%0], 0, 0x989680;\n\t"
        "@P1 bra.uni D_%=;\n\t"
        "bra.uni W_%=;\n\t"
        "D_%=:\n\t"
        "}"
        :: "r"(my_mbar) : "memory");

    const unsigned char* wsrc = stage + (size_t)t0 * TAB_STRIDE;
    float* gbase = out + (size_t)base * (POS_BYTES / 4) + (size_t)t0 * SLOT;
    #pragma unroll
    for (int i = 0; i < 10; i++) {
        const int f   = i * 32 + lane;
        const int tt  = f / 80;
        const int rem = f - tt * 80;
        const int p   = rem / 20;
        const int q   = rem - p * 20;
        const float4 v = *(const float4*)(wsrc + (tt * P4 + p) * ROW_BYTES + q * 16);
        __stcs((float4*)(gbase + (size_t)p * (POS_BYTES / 4) + tt * SLOT + q * 4), v);
    }
}

// ==================== fallback 2: R7-style (no tensor maps at all) ====================
#define FB_P       4
#define FB_THREADS (FB_P * NTAB)
#define FB_STAGE   (FB_P * POS_BYTES)
#define FB_BLOCKS  (NPOS / FB_P)

__global__ __launch_bounds__(FB_THREADS) void engram_fb_kernel(
    const int* __restrict__ ids,
    const int* __restrict__ seeds,
    Tables tp,
    float* __restrict__ out)
{
    __shared__ __align__(16) unsigned char stage[FB_STAGE];
    __shared__ __align__(8)  unsigned long long mbar[FB_P];

    const int tid = threadIdx.x;
    const uint32_t stage_a = smem_u32(stage);
    const uint32_t mbar_a0 = smem_u32(mbar);

    if (tid < FB_P) {
        asm volatile("mbarrier.init.shared.b64 [%0], 1;"
                     :: "r"(mbar_a0 + tid * 8) : "memory");
    }
    __syncthreads();

    const int p    = tid >> 4;
    const int tab  = tid & 15;
    const int pos  = blockIdx.x * FB_P + p;
    const uint32_t my_mbar = mbar_a0 + p * 8;

    uint64_t pol_ef, pol_el;
    asm("createpolicy.fractional.L2::evict_first.b64 %0, 1.0;" : "=l"(pol_ef));
    asm("createpolicy.fractional.L2::evict_last.b64 %0, 1.0;"  : "=l"(pol_el));

    const unsigned int idx =
        (unsigned int)hash_idx(ids, seeds, tab, pos, (unsigned long long)c_sizes[tab]);

    if (tab == 0) {
        asm volatile("mbarrier.arrive.expect_tx.shared.b64 _, [%0], %1;"
                     :: "r"(my_mbar), "r"((int)POS_BYTES) : "memory");
    }
    {
        const char*    src = (const char*)tp.t[tab] + (size_t)idx * ROW_BYTES;
        const uint32_t dst = stage_a + (uint32_t)tid * ROW_BYTES;
        asm volatile(
            "cp.async.bulk.shared::cta.global.mbarrier::complete_tx::bytes.L2::cache_hint "
            "[%0], [%1], %2, [%3], %4;"
            :: "r"(dst), "l"(src), "r"((int)ROW_BYTES), "r"(my_mbar), "l"(pol_el)
            : "memory");
    }

    if (tab == 0) {
        asm volatile(
            "{\n\t"
            ".reg .pred P1;\n\t"
            "W_%=:\n\t"
            "mbarrier.try_wait.parity.shared.b64 P1, [%0], 0, 0x989680;\n\t"
            "@P1 bra.uni D_%=;\n\t"
            "bra.uni W_%=;\n\t"
            "D_%=:\n\t"
            "}"
            :: "r"(my_mbar) : "memory");

        char* gdst = (char*)out + (size_t)pos * POS_BYTES;
        asm volatile(
            "cp.async.bulk.global.shared::cta.bulk_group.L2::cache_hint "
            "[%0], [%1], %2, %3;"
            :: "l"(gdst), "r"(stage_a + (uint32_t)p * POS_BYTES), "r"((int)POS_BYTES),
               "l"(pol_ef)
            : "memory");
        asm volatile("cp.async.bulk.commit_group;" ::: "memory");
        asm volatile("cp.async.bulk.wait_group.read 0;" ::: "memory");
    }
}

// ==================== host ====================
typedef CUresult (*PFN_encodeTiled)(
    CUtensorMap*, CUtensorMapDataType, cuuint32_t, void*,
    const cuuint64_t*, const cuuint64_t*, const cuuint32_t*, const cuuint32_t*,
    CUtensorMapInterleave, CUtensorMapSwizzle, CUtensorMapL2promotion,
    CUtensorMapFloatOOBfill);

extern "C" void kernel_launch(void* const* d_in, const int* in_sizes, int n_in,
                              void* d_out, int out_size)
{
    const int* ids   = (const int*)d_in[0];
    const int* seeds = (const int*)d_in[1];

    bool ok = false;       // 16 table maps encoded
    bool ok_out = false;   // output 3D map encoded (box z=8)
    TMaps maps;
    void* fp = nullptr;
    cudaDriverEntryPointQueryResult qres;
    if (cudaGetDriverEntryPointByVersion("cuTensorMapEncodeTiled", &fp, 12000,
                                         cudaEnableDefault, &qres) == cudaSuccess
        && fp != nullptr) {
        PFN_encodeTiled enc = (PFN_encodeTiled)fp;
        ok = true;
        for (int t = 0; t < 16 && ok; t++) {
            cuuint64_t dims[2]    = {(cuuint64_t)SLOT, (cuuint64_t)h_sizes[t]};
            cuuint64_t strides[1] = {(cuuint64_t)ROW_BYTES};
            cuuint32_t box[2]     = {(cuuint32_t)SLOT, 1u};
            cuuint32_t estr[2]    = {1u, 1u};
            CUresult r = enc(&maps.m[t], CU_TENSOR_MAP_DATA_TYPE_FLOAT32, 2,
                             (void*)d_in[2 + t], dims, strides, box, estr,
                             CU_TENSOR_MAP_INTERLEAVE_NONE,
                             CU_TENSOR_MAP_SWIZZLE_NONE,
                             CU_TENSOR_MAP_L2_PROMOTION_L2_128B,
                             CU_TENSOR_MAP_FLOAT_OOB_FILL_NONE);
            if (r != CUDA_SUCCESS) ok = false;
        }
        if (ok) {
            // output as 3D tensor [pos][tab][80 floats], store box (80,1,8)
            cuuint64_t dims[3]    = {(cuuint64_t)SLOT, (cuuint64_t)NTAB, (cuuint64_t)NPOS};
            cuuint64_t strides[2] = {(cuuint64_t)ROW_BYTES, (cuuint64_t)POS_BYTES};
            cuuint32_t box[3]     = {(cuuint32_t)SLOT, 1u, (cuuint32_t)P8};
            cuuint32_t estr[3]    = {1u, 1u, 1u};
            CUresult r = enc(&maps.m[16], CU_TENSOR_MAP_DATA_TYPE_FLOAT32, 3,
                             d_out, dims, strides, box, estr,
                             CU_TENSOR_MAP_INTERLEAVE_NONE,
                             CU_TENSOR_MAP_SWIZZLE_NONE,
                             CU_TENSOR_MAP_L2_PROMOTION_L2_128B,
                             CU_TENSOR_MAP_FLOAT_OOB_FILL_NONE);
            ok_out = (r == CUDA_SUCCESS);
        }
    }

    if (ok && ok_out) {
        engram_g8_kernel<<<G8_BLOCKS, G8_THREADS>>>(ids, seeds, maps);
    } else if (ok) {
        engram_g4stg_kernel<<<G4_BLOCKS, G8_THREADS>>>(ids, seeds, maps, (float*)d_out);
    } else {
        Tables tp;
        for (int i = 0; i < 16; i++) tp.t[i] = (const float*)d_in[2 + i];
        engram_fb_kernel<<<FB_BLOCKS, FB_THREADS>>>(ids, seeds, tp, (float*)d_out);
    }
}